// round 1
// baseline (speedup 1.0000x reference)
#include <cuda_runtime.h>
#include <math.h>

typedef unsigned long long u64;
typedef unsigned int u32;

#define NB 16
#define NC 80
#define NCAND 3267
#define NFLAT (NCAND * NC)      // 261360
#define KSEL 1000
#define NEGF (-1e30f)
#define LTHRF (-2.9444389791664403f)

// level tables
// hw:      15200, 3800, 950, 247, 70
// stride:  8, 16, 32, 64, 128
// rowbase: 0, 1000, 2000, 2950, 3197

// ---------------- scratch (static device memory; no allocations) ----------------
__device__ float d_max[NB][19000];                 // per-loc max logit, lvl0 [0,15200), lvl1 [15200,19000)
__device__ int   d_sel_loc[NB][2][KSEL];           // per-level selected locations (topk order)
__device__ float d_cand_logits[NB][NFLAT];         // candidate logits [3267][80]
__device__ float d_cand_boxes[NB][NCAND][4];       // decoded (pre-clip) boxes
__device__ float d_topb[NB][KSEL][4];              // clipped boxes of 1000 selected
__device__ float4 d_nb[NB][KSEL];                  // class-offset boxes
__device__ float d_tops[NB][KSEL];
__device__ int   d_lab[NB][KSEL];
__device__ unsigned char d_validf[NB][KSEL];

// ---------------- helpers ----------------
__device__ __forceinline__ u32 ford(float f) {
    u32 u = __float_as_uint(f);
    return (u & 0x80000000u) ? ~u : (u | 0x80000000u);
}

struct KeySmem {
    const float* vals;
    __device__ __forceinline__ u64 operator()(int i) const {
        return ((u64)ford(vals[i]) << 32) | (u64)(0xFFFFFFFFu - (u32)i);
    }
};
struct KeyFlat {
    const float* lp;
    __device__ __forceinline__ u64 operator()(int i) const {
        float v = __ldg(lp + i);
        float vv = (v > LTHRF) ? v : NEGF;
        return ((u64)ford(vv) << 32) | (u64)(0xFFFFFFFFu - (u32)i);
    }
};

// exact radix-select of K-th largest 64-bit key (keys unique by construction)
template <typename KeyF>
__device__ u64 radix_select_k(KeyF keyf, int n, int K, u32* hist, u64* s_prefix, int* s_krem) {
    u64 prefix = 0;
    int krem = K;
    for (int d = 7; d >= 0; --d) {
        for (int t = threadIdx.x; t < 256; t += blockDim.x) hist[t] = 0;
        __syncthreads();
        for (int i = threadIdx.x; i < n; i += blockDim.x) {
            u64 key = keyf(i);
            bool ok;
            if (d == 7) ok = true;
            else        ok = ((key >> ((d + 1) * 8)) == prefix);
            if (ok) atomicAdd(&hist[(u32)(key >> (d * 8)) & 255u], 1u);
        }
        __syncthreads();
        if (threadIdx.x == 0) {
            int c = 0;
            int b = 255;
            for (; b > 0; --b) {
                int h = (int)hist[b];
                if (c + h >= krem) break;
                c += h;
            }
            *s_prefix = (prefix << 8) | (u32)b;
            *s_krem = krem - c;
        }
        __syncthreads();
        prefix = *s_prefix;
        krem = *s_krem;
        __syncthreads();
    }
    return prefix;
}

// ascending bitonic sort of 1024 u64 keys in shared memory; blockDim.x must be 1024
__device__ void bitonic_sort_1024(u64* s) {
    int tid = threadIdx.x;
    for (int k = 2; k <= 1024; k <<= 1) {
        for (int j = k >> 1; j > 0; j >>= 1) {
            int ixj = tid ^ j;
            if (ixj > tid) {
                u64 a = s[tid], b = s[ixj];
                bool up = ((tid & k) == 0);
                if ((a > b) == up) { s[tid] = b; s[ixj] = a; }
            }
            __syncthreads();
        }
    }
}

// ---------------- K0: per-location max logit, levels 0 & 1 ----------------
__global__ void k0_maxlogit(const float* __restrict__ cls0, const float* __restrict__ cls1) {
    int idx = blockIdx.x * blockDim.x + threadIdx.x;
    if (idx >= NB * 19000) return;
    int img = idx / 19000;
    int r = idx % 19000;
    const float* base;
    int hw, loc;
    if (r < 15200) { hw = 15200; loc = r;         base = cls0 + (size_t)img * NC * 15200; }
    else           { hw = 3800;  loc = r - 15200; base = cls1 + (size_t)img * NC * 3800; }
    float m = __int_as_float(0xff800000);
#pragma unroll 8
    for (int c = 0; c < NC; c++) m = fmaxf(m, __ldg(base + (size_t)c * hw + loc));
    d_max[img][r] = m;
}

// ---------------- K1: per (img, level) top-1000 locations ----------------
// smem: vals[15200] f32 | sel[1024] u64 | hist[256] u32 | prefix u64 | krem,cnt
#define K1_SMEM (60800 + 8192 + 1024 + 32)
__global__ void k1_select() {
    extern __shared__ char sm[];
    float* s_vals = (float*)sm;
    u64* s_sel = (u64*)(sm + 60800);
    u32* hist = (u32*)(sm + 60800 + 8192);
    u64* s_prefix = (u64*)(sm + 60800 + 8192 + 1024);
    int* s_krem = (int*)(sm + 60800 + 8192 + 1024 + 8);
    int* s_cnt = (int*)(sm + 60800 + 8192 + 1024 + 12);

    int lvl = blockIdx.x;
    int img = blockIdx.y;
    int n = lvl ? 3800 : 15200;
    int off = lvl ? 15200 : 0;

    for (int i = threadIdx.x; i < n; i += blockDim.x) s_vals[i] = d_max[img][off + i];
    __syncthreads();

    KeySmem kf{s_vals};
    u64 kth = radix_select_k(kf, n, KSEL, hist, s_prefix, s_krem);

    if (threadIdx.x == 0) *s_cnt = 0;
    __syncthreads();
    for (int i = threadIdx.x; i < n; i += blockDim.x) {
        u64 key = kf(i);
        if (key >= kth) {
            int p = atomicAdd(s_cnt, 1);
            if (p < 1024) s_sel[p] = key;
        }
    }
    __syncthreads();
    int cnt = *s_cnt;
    if ((int)threadIdx.x >= cnt) s_sel[threadIdx.x] = 0;
    __syncthreads();
    bitonic_sort_1024(s_sel);
    if (threadIdx.x < KSEL) {
        u64 key = s_sel[1023 - threadIdx.x];
        d_sel_loc[img][lvl][threadIdx.x] = (int)(0xFFFFFFFFu - (u32)(key & 0xFFFFFFFFull));
    }
}

// ---------------- row -> (level, loc) mapping ----------------
__device__ __forceinline__ void row_to_lvl_loc(int img, int row, int& lvl, int& loc) {
    if (row < 1000)      { lvl = 0; loc = d_sel_loc[img][0][row]; }
    else if (row < 2000) { lvl = 1; loc = d_sel_loc[img][1][row - 1000]; }
    else if (row < 2950) { lvl = 2; loc = row - 2000; }
    else if (row < 3197) { lvl = 3; loc = row - 2950; }
    else                 { lvl = 4; loc = row - 3197; }
}

// ---------------- K2a: gather candidate logits ----------------
__global__ void k2_logits(const float* __restrict__ c0, const float* __restrict__ c1,
                          const float* __restrict__ c2, const float* __restrict__ c3,
                          const float* __restrict__ c4) {
    int j = blockIdx.x * blockDim.x + threadIdx.x;
    if (j >= NFLAT) return;
    int img = blockIdx.y;
    int row = j / NC, c = j % NC;
    int lvl, loc;
    row_to_lvl_loc(img, row, lvl, loc);
    const float* p;
    int hw;
    switch (lvl) {
        case 0: p = c0; hw = 15200; break;
        case 1: p = c1; hw = 3800; break;
        case 2: p = c2; hw = 950; break;
        case 3: p = c3; hw = 247; break;
        default: p = c4; hw = 70; break;
    }
    d_cand_logits[img][j] = __ldg(p + ((size_t)img * NC + c) * hw + loc);
}

// ---------------- K2b: decode candidate boxes ----------------
__global__ void k2_boxes(const float* __restrict__ r0, const float* __restrict__ r1,
                         const float* __restrict__ r2, const float* __restrict__ r3,
                         const float* __restrict__ r4, const int* __restrict__ isz) {
    int row = blockIdx.x * blockDim.x + threadIdx.x;
    if (row >= NCAND) return;
    int img = blockIdx.y;
    int lvl, loc;
    row_to_lvl_loc(img, row, lvl, loc);
    const float* p;
    int hw;
    float sf;
    switch (lvl) {
        case 0: p = r0; hw = 15200; sf = 8.f; break;
        case 1: p = r1; hw = 3800; sf = 16.f; break;
        case 2: p = r2; hw = 950; sf = 32.f; break;
        case 3: p = r3; hw = 247; sf = 64.f; break;
        default: p = r4; hw = 70; sf = 128.f; break;
    }
    float hF = (float)__ldg(isz + img * 2);
    float wF = (float)__ldg(isz + img * 2 + 1);
    size_t base = (size_t)img * 4 * hw;
    float v0 = __ldg(p + base + 0 * (size_t)hw + loc);
    float v1 = __ldg(p + base + 1 * (size_t)hw + loc);
    float v2 = __ldg(p + base + 2 * (size_t)hw + loc);
    float v3 = __ldg(p + base + 3 * (size_t)hw + loc);
    // reshape(-1,2)*s min hwf -> permute [1,0,3,2]
    d_cand_boxes[img][row][0] = fminf(__fmul_rn(v1, sf), wF);
    d_cand_boxes[img][row][1] = fminf(__fmul_rn(v0, sf), hF);
    d_cand_boxes[img][row][2] = fminf(__fmul_rn(v3, sf), wF);
    d_cand_boxes[img][row][3] = fminf(__fmul_rn(v2, sf), hF);
}

// ---------------- K3: per-image global top-1000 over flattened scores ----------------
__global__ void k3_flat(const int* __restrict__ isz) {
    __shared__ u64 s_sel[1024];
    __shared__ u32 hist[256];
    __shared__ u64 s_prefix;
    __shared__ int s_krem, s_cnt;
    __shared__ float s_redf[1024];
    __shared__ float s_mc;

    int img = blockIdx.x;
    int tid = threadIdx.x;
    const float* lp = d_cand_logits[img];
    KeyFlat kf{lp};
    u64 kth = radix_select_k(kf, NFLAT, KSEL, hist, &s_prefix, &s_krem);

    if (tid == 0) s_cnt = 0;
    __syncthreads();
    for (int i = tid; i < NFLAT; i += blockDim.x) {
        u64 key = kf(i);
        if (key >= kth) {
            int p = atomicAdd(&s_cnt, 1);
            if (p < 1024) s_sel[p] = key;
        }
    }
    __syncthreads();
    int cnt = s_cnt;
    if (tid >= cnt) s_sel[tid] = 0;
    __syncthreads();
    bitonic_sort_1024(s_sel);

    float hF = (float)__ldg(isz + img * 2);
    float wF = (float)__ldg(isz + img * 2 + 1);

    float x1c = 0.f, y1c = 0.f, x2c = 0.f, y2c = 0.f, mylocal = 0.f;
    int lab = 0;
    bool val = false;
    if (tid < KSEL) {
        u64 key = s_sel[1023 - tid];
        u32 idx = 0xFFFFFFFFu - (u32)(key & 0xFFFFFFFFull);
        float logit = __ldg(lp + idx);
        val = (logit > LTHRF);
        float tops = val ? (1.f / (1.f + expf(-logit))) : NEGF;
        int row = idx / NC;
        lab = (int)(idx % NC) + 1;
        const float* bx = d_cand_boxes[img][row];
        float b0 = bx[0], b1 = bx[1];
        float b2 = fmaxf(__fadd_rn(b0, 1.f), bx[2]);
        float b3 = fmaxf(__fadd_rn(b1, 1.f), bx[3]);
        float wm1 = __fsub_rn(wF, 1.f), hm1 = __fsub_rn(hF, 1.f);
        x1c = fminf(fmaxf(b0, 0.f), wm1);
        y1c = fminf(fmaxf(b1, 0.f), hm1);
        x2c = fminf(fmaxf(b2, 0.f), wm1);
        y2c = fminf(fmaxf(b3, 0.f), hm1);
        d_topb[img][tid][0] = x1c;
        d_topb[img][tid][1] = y1c;
        d_topb[img][tid][2] = x2c;
        d_topb[img][tid][3] = y2c;
        d_tops[img][tid] = tops;
        d_lab[img][tid] = lab;
        d_validf[img][tid] = val ? 1 : 0;
        if (val) mylocal = fmaxf(fmaxf(x1c, y1c), fmaxf(x2c, y2c));
    }
    s_redf[tid] = mylocal;
    __syncthreads();
    for (int s = 512; s > 0; s >>= 1) {
        if (tid < s) s_redf[tid] = fmaxf(s_redf[tid], s_redf[tid + s]);
        __syncthreads();
    }
    if (tid == 0) s_mc = s_redf[0];
    __syncthreads();
    if (tid < KSEL) {
        float mc1 = __fadd_rn(s_mc, 1.f);
        float o = __fmul_rn((float)lab, mc1);
        d_nb[img][tid] = make_float4(__fadd_rn(x1c, o), __fadd_rn(y1c, o),
                                     __fadd_rn(x2c, o), __fadd_rn(y2c, o));
    }
}

// ---------------- K4: NMS + final top-100 + output ----------------
// smem: nb float4[1000]=16000 | area f32[1000]=4000 | mask u64[1000*16]=128000 |
//       valid u8[1000]=1000 | final int[100]=400 | keepw u64[16]=128 | nkeep int
#define K4_SMEM (16000 + 4000 + 128000 + 1000 + 400 + 128 + 16)
__global__ void k4_nms(float* __restrict__ out) {
    extern __shared__ char sm[];
    float4* s_nb = (float4*)sm;
    float* s_area = (float*)(sm + 16000);
    u64* s_mask = (u64*)(sm + 20000);
    unsigned char* s_valid = (unsigned char*)(sm + 148000);
    int* s_final = (int*)(sm + 149000);
    u64* s_keepw = (u64*)(sm + 149400);
    int* s_nkeep = (int*)(sm + 149528);

    int img = blockIdx.x;
    int tid = threadIdx.x;

    for (int i = tid; i < KSEL; i += blockDim.x) {
        float4 nb = d_nb[img][i];
        s_nb[i] = nb;
        s_area[i] = __fmul_rn(__fsub_rn(nb.z, nb.x), __fsub_rn(nb.w, nb.y));
        s_valid[i] = d_validf[img][i];
    }
    __syncthreads();

    // suppression bitmask: for row i, word w holds bits for j in [64w, 64w+64) with j<i
    for (int t = tid; t < 16000; t += blockDim.x) {
        int w = t / 1000;
        int i = t % 1000;
        int j0 = w * 64;
        int j1 = min(j0 + 64, i);
        u64 m = 0;
        if (j1 > j0) {
            float4 A = s_nb[i];
            float aA = s_area[i];
            for (int j = j0; j < j1; ++j) {
                float4 Bb = s_nb[j];
                float ix1 = fmaxf(A.x, Bb.x), iy1 = fmaxf(A.y, Bb.y);
                float ix2 = fminf(A.z, Bb.z), iy2 = fminf(A.w, Bb.w);
                float iw = fmaxf(__fsub_rn(ix2, ix1), 0.f);
                float ih = fmaxf(__fsub_rn(iy2, iy1), 0.f);
                float inter = __fmul_rn(iw, ih);
                float den = fmaxf(__fsub_rn(__fadd_rn(aA, s_area[j]), inter), 1e-9f);
                float iou = __fdiv_rn(inter, den);
                if (iou > 0.6f) m |= (1ull << (j - j0));
            }
        }
        s_mask[i * 16 + w] = m;
    }
    __syncthreads();

    // serial greedy scan, warp 0, lanes 0..15 own one u64 keep word each
    if (tid < 32) {
        int lane = tid;
        u64 keepw = 0;
        int nk = 0;
        u64 next = (lane < 16) ? s_mask[lane] : 0;
        for (int i = 0; i < 1000; i++) {
            u64 rowm = next;
            next = (lane < 16 && i < 999) ? s_mask[(i + 1) * 16 + lane] : 0;
            bool sup = (rowm & keepw) != 0;
            bool any = __any_sync(0xFFFFFFFFu, sup);
            bool keep = (s_valid[i] != 0) && !any;
            if (keep) {
                if ((i >> 6) == lane) keepw |= (1ull << (i & 63));
                if (lane == 0 && nk < 100) s_final[nk] = i;
                nk++;
            }
        }
        if (lane < 16) s_keepw[lane] = keepw;
        __syncwarp();
        if (lane == 0) {
            int cnt = nk < 100 ? nk : 100;
            *s_nkeep = cnt;
            for (int i = 0; i < 1000 && cnt < 100; i++) {
                bool kb = (s_keepw[i >> 6] >> (i & 63)) & 1ull;
                if (!kb) s_final[cnt++] = i;
            }
        }
    }
    __syncthreads();

    if (tid < 100) {
        int fi = s_final[tid];
        bool v = tid < *s_nkeep;
        const float* bp = d_topb[img][fi];
        int base = img * 100 + tid;
        out[base * 4 + 0] = bp[0];
        out[base * 4 + 1] = bp[1];
        out[base * 4 + 2] = bp[2];
        out[base * 4 + 3] = bp[3];
        out[6400 + base] = v ? d_tops[img][fi] : 0.f;
        out[8000 + base] = (float)d_lab[img][fi];
        out[9600 + base] = v ? 1.f : 0.f;
    }
}

// ---------------- host launcher ----------------
extern "C" void kernel_launch(void* const* d_in, const int* in_sizes, int n_in,
                              void* d_out, int out_size) {
    static const int clsN[5] = {19456000, 4864000, 1216000, 316160, 89600};
    static const int regN[5] = {972800, 243200, 60800, 15808, 4480};
    const float* cls[5] = {0, 0, 0, 0, 0};
    const float* reg[5] = {0, 0, 0, 0, 0};
    const int* isz = 0;
    for (int i = 0; i < n_in; i++) {
        int s = in_sizes[i];
        if (s == 32) { isz = (const int*)d_in[i]; continue; }
        for (int l = 0; l < 5; l++) {
            if (s == clsN[l]) cls[l] = (const float*)d_in[i];
            if (s == regN[l]) reg[l] = (const float*)d_in[i];
        }
    }
    if (!isz) return;
    for (int l = 0; l < 5; l++) if (!cls[l] || !reg[l]) return;

    cudaFuncSetAttribute(k1_select, cudaFuncAttributeMaxDynamicSharedMemorySize, K1_SMEM);
    cudaFuncSetAttribute(k4_nms, cudaFuncAttributeMaxDynamicSharedMemorySize, K4_SMEM);

    k0_maxlogit<<<(NB * 19000 + 255) / 256, 256>>>(cls[0], cls[1]);
    k1_select<<<dim3(2, NB), 1024, K1_SMEM>>>();
    k2_logits<<<dim3((NFLAT + 255) / 256, NB), 256>>>(cls[0], cls[1], cls[2], cls[3], cls[4]);
    k2_boxes<<<dim3((NCAND + 255) / 256, NB), 256>>>(reg[0], reg[1], reg[2], reg[3], reg[4], isz);
    k3_flat<<<NB, 1024>>>(isz);
    k4_nms<<<NB, 1024, K4_SMEM>>>((float*)d_out);
}

// round 3
// speedup vs baseline: 1.5857x; 1.5857x over previous
#include <cuda_runtime.h>
#include <math.h>

typedef unsigned long long u64;
typedef unsigned int u32;
typedef unsigned char u8;

#define NB 16
#define NC 80
#define NCAND 3267
#define NFLAT (NCAND * NC)      // 261360
#define KSEL 1000
#define NEGF (-1e30f)
#define LTHRF (-2.9444389791664403f)
#define KCAP 16384
#define NCHUNK 32

// level tables: hw = 15200,3800,950,247,70 ; stride = 8,16,32,64,128 ; rowbase = 0,1000,2000,2950,3197

// ---------------- scratch (static device memory) ----------------
__device__ float d_max[NB][19000];
__device__ int   d_sel_loc[NB][2][KSEL];
__device__ float d_cand_logits[NB][NFLAT];
__device__ u32   d_hist[NB][256];
__device__ int   d_cnt[NB];
__device__ u64   d_keys[NB][KCAP];

// ---------------- helpers ----------------
__device__ __forceinline__ u32 ford(float f) {
    u32 u = __float_as_uint(f);
    return (u & 0x80000000u) ? ~u : (u | 0x80000000u);
}
__device__ __forceinline__ float iford(u32 o) {
    u32 u = (o & 0x80000000u) ? (o & 0x7FFFFFFFu) : ~o;
    return __uint_as_float(u);
}

struct KeyArr64 {
    const u64* k;
    __device__ __forceinline__ u64 operator()(int i) const { return k[i]; }
};

// exact radix-select of K-th largest 64-bit key (unique keys)
template <typename KeyF>
__device__ u64 radix_select_k(KeyF keyf, int n, int K, u32* hist, u64* s_prefix, int* s_krem) {
    u64 prefix = 0;
    int krem = K;
    for (int d = 7; d >= 0; --d) {
        for (int t = threadIdx.x; t < 256; t += blockDim.x) hist[t] = 0;
        __syncthreads();
        for (int i = threadIdx.x; i < n; i += blockDim.x) {
            u64 key = keyf(i);
            bool ok = (d == 7) || ((key >> ((d + 1) * 8)) == prefix);
            if (ok) atomicAdd(&hist[(u32)(key >> (d * 8)) & 255u], 1u);
        }
        __syncthreads();
        if (threadIdx.x == 0) {
            int c = 0;
            int b = 255;
            for (; b > 0; --b) {
                int h = (int)hist[b];
                if (c + h >= krem) break;
                c += h;
            }
            *s_prefix = (prefix << 8) | (u32)b;
            *s_krem = krem - c;
        }
        __syncthreads();
        prefix = *s_prefix;
        krem = *s_krem;
        __syncthreads();
    }
    return prefix;
}

// radix-select of K-th largest 32-bit key (ties possible -> caller compacts >=)
template <typename KeyF32>
__device__ u32 radix_select_k32(KeyF32 keyf, int n, int K, u32* hist, u32* s_prefix, int* s_krem) {
    u32 prefix = 0;
    int krem = K;
    for (int d = 3; d >= 0; --d) {
        for (int t = threadIdx.x; t < 256; t += blockDim.x) hist[t] = 0;
        __syncthreads();
        for (int i = threadIdx.x; i < n; i += blockDim.x) {
            u32 key = keyf(i);
            bool ok = (d == 3) || ((key >> ((d + 1) * 8)) == prefix);
            if (ok) atomicAdd(&hist[(key >> (d * 8)) & 255u], 1u);
        }
        __syncthreads();
        if (threadIdx.x == 0) {
            int c = 0;
            int b = 255;
            for (; b > 0; --b) {
                int h = (int)hist[b];
                if (c + h >= krem) break;
                c += h;
            }
            *s_prefix = (prefix << 8) | (u32)b;
            *s_krem = krem - c;
        }
        __syncthreads();
        prefix = *s_prefix;
        krem = *s_krem;
        __syncthreads();
    }
    return prefix;
}

// ascending bitonic sort of 1024 u64 keys; blockDim.x must be 1024
__device__ void bitonic_sort_1024(u64* s) {
    int tid = threadIdx.x;
    for (int k = 2; k <= 1024; k <<= 1) {
        for (int j = k >> 1; j > 0; j >>= 1) {
            int ixj = tid ^ j;
            if (ixj > tid) {
                u64 a = s[tid], b = s[ixj];
                bool up = ((tid & k) == 0);
                if ((a > b) == up) { s[tid] = b; s[ixj] = a; }
            }
            __syncthreads();
        }
    }
}

// ---------------- K0: per-location max logit (levels 0,1), float4, + scratch zero ----------------
__global__ void k0_maxlogit(const float4* __restrict__ cls0, const float4* __restrict__ cls1) {
    int idx = blockIdx.x * blockDim.x + threadIdx.x;
    if (idx < NB * 256) ((u32*)d_hist)[idx] = 0;
    if (idx < NB) d_cnt[idx] = 0;
    if (idx >= NB * 4750) return;
    int img = idx / 4750;
    int r4 = idx % 4750;
    const float4* base;
    int hw4, loc4, outoff;
    if (r4 < 3800) { base = cls0 + (size_t)img * NC * 3800; hw4 = 3800; loc4 = r4;       outoff = r4 * 4; }
    else           { base = cls1 + (size_t)img * NC * 950;  hw4 = 950;  loc4 = r4 - 3800; outoff = 15200 + (r4 - 3800) * 4; }
    float ninf = __int_as_float(0xff800000);
    float4 m = make_float4(ninf, ninf, ninf, ninf);
#pragma unroll 8
    for (int c = 0; c < NC; c++) {
        float4 v = __ldg(base + (size_t)c * hw4 + loc4);
        m.x = fmaxf(m.x, v.x); m.y = fmaxf(m.y, v.y);
        m.z = fmaxf(m.z, v.z); m.w = fmaxf(m.w, v.w);
    }
    *(float4*)&d_max[img][outoff] = m;
}

// ---------------- K1: per (img, level) top-1000 locations (32-bit select + 64-bit tie sort) ----------------
#define K1_SMEM (60800 + 8192 + 1024 + 32)
struct KeyVal32 {
    const float* v;
    __device__ __forceinline__ u32 operator()(int i) const { return ford(v[i]); }
};
__global__ void k1_select() {
    extern __shared__ char sm[];
    float* s_vals = (float*)sm;
    u64* s_sel = (u64*)(sm + 60800);
    u32* hist = (u32*)(sm + 60800 + 8192);
    u32* s_prefix = (u32*)(sm + 60800 + 8192 + 1024);
    int* s_krem = (int*)(sm + 60800 + 8192 + 1024 + 8);
    int* s_cnt = (int*)(sm + 60800 + 8192 + 1024 + 12);

    int lvl = blockIdx.x;
    int img = blockIdx.y;
    int n = lvl ? 3800 : 15200;
    int off = lvl ? 15200 : 0;

    for (int i = threadIdx.x; i < n; i += blockDim.x) s_vals[i] = d_max[img][off + i];
    __syncthreads();

    KeyVal32 kf{s_vals};
    u32 v32 = radix_select_k32(kf, n, KSEL, hist, s_prefix, s_krem);

    if (threadIdx.x == 0) *s_cnt = 0;
    __syncthreads();
    for (int i = threadIdx.x; i < n; i += blockDim.x) {
        u32 o = ford(s_vals[i]);
        if (o >= v32) {
            int p = atomicAdd(s_cnt, 1);
            if (p < 1024) s_sel[p] = ((u64)o << 32) | (u64)(0xFFFFFFFFu - (u32)i);
        }
    }
    __syncthreads();
    int cnt = *s_cnt;
    if ((int)threadIdx.x >= cnt) s_sel[threadIdx.x] = 0;
    __syncthreads();
    bitonic_sort_1024(s_sel);
    if (threadIdx.x < KSEL) {
        u64 key = s_sel[1023 - threadIdx.x];
        d_sel_loc[img][lvl][threadIdx.x] = (int)(0xFFFFFFFFu - (u32)(key & 0xFFFFFFFFull));
    }
}

// ---------------- row -> (level, loc) mapping ----------------
__device__ __forceinline__ void row_to_lvl_loc(int img, int row, int& lvl, int& loc) {
    if (row < 1000)      { lvl = 0; loc = d_sel_loc[img][0][row]; }
    else if (row < 2000) { lvl = 1; loc = d_sel_loc[img][1][row - 1000]; }
    else if (row < 2950) { lvl = 2; loc = row - 2000; }
    else if (row < 3197) { lvl = 3; loc = row - 2950; }
    else                 { lvl = 4; loc = row - 3197; }
}

// ---------------- K2a: gather candidate logits + top-byte histogram (fused) ----------------
__global__ void k2a_gather_hist(const float* __restrict__ c0, const float* __restrict__ c1,
                                const float* __restrict__ c2, const float* __restrict__ c3,
                                const float* __restrict__ c4) {
    __shared__ u32 sh[256];
    int tid = threadIdx.x;
    for (int t = tid; t < 256; t += blockDim.x) sh[t] = 0;
    __syncthreads();

    int j = blockIdx.x * blockDim.x + tid;
    int img = blockIdx.y;
    if (j < NFLAT) {
        int row = j / NC, c = j % NC;
        int lvl, loc;
        row_to_lvl_loc(img, row, lvl, loc);
        const float* p;
        int hw;
        switch (lvl) {
            case 0: p = c0; hw = 15200; break;
            case 1: p = c1; hw = 3800; break;
            case 2: p = c2; hw = 950; break;
            case 3: p = c3; hw = 247; break;
            default: p = c4; hw = 70; break;
        }
        float v = __ldg(p + ((size_t)img * NC + c) * hw + loc);
        d_cand_logits[img][j] = v;
        float vv = (v > LTHRF) ? v : NEGF;
        atomicAdd(&sh[ford(vv) >> 24], 1u);
    }
    __syncthreads();
    for (int t = tid; t < 256; t += blockDim.x)
        if (sh[t]) atomicAdd(&d_hist[img][t], sh[t]);
}

// ---------------- K3b: find boundary byte, compact surviving keys ----------------
__global__ void k3b_compact() {
    __shared__ u32 s_suf[256];
    __shared__ int s_bstar;
    int img = blockIdx.y;
    int chunk = blockIdx.x;
    int tid = threadIdx.x;
    if (tid < 256) s_suf[tid] = d_hist[img][tid];
    __syncthreads();
    // inclusive suffix sum over 256 bins
    for (int s = 1; s < 256; s <<= 1) {
        u32 v = 0;
        if (tid < 256) {
            v = s_suf[tid];
            if (tid + s < 256) v += s_suf[tid + s];
        }
        __syncthreads();
        if (tid < 256) s_suf[tid] = v;
        __syncthreads();
    }
    if (tid < 256) {
        if (s_suf[tid] >= KSEL && (tid == 255 || s_suf[tid + 1] < KSEL)) s_bstar = tid;
    }
    __syncthreads();
    u32 bstar = (u32)s_bstar;
    int per = (NFLAT + NCHUNK - 1) / NCHUNK;
    int i0 = chunk * per;
    int i1 = min(i0 + per, NFLAT);
    const float* lp = d_cand_logits[img];
    for (int i = i0 + tid; i < i1; i += blockDim.x) {
        float v = __ldg(lp + i);
        float vv = (v > LTHRF) ? v : NEGF;
        u32 o = ford(vv);
        if ((o >> 24) >= bstar) {
            int p = atomicAdd(&d_cnt[img], 1);
            if (p < KCAP) d_keys[img][p] = ((u64)o << 32) | (u64)(0xFFFFFFFFu - (u32)i);
        }
    }
}

// ---------------- K3c: exact top-1000 + epilogue + NMS + output (fused) ----------------
// smem layout (bytes):
#define O_KEYS   0               // u64[16384] = 131072, reused as mask u64[16000]
#define O_SEL    131072          // u64[1024]  = 8192
#define O_HIST   139264          // u32[256]   = 1024
#define O_MISC   140288          // prefix u64 | krem | cnt2 | nkeep | mc  (32)
#define O_REDF   140320          // float[1024] = 4096
#define O_NB     144416          // float4[1000] = 16000
#define O_AREA   160416          // float[1000] = 4000
#define O_TOPB   164416          // float4[1000] = 16000
#define O_TOPS   180416          // float[1000] = 4000
#define O_LAB    184416          // int[1000] = 4000
#define O_VALID  188416          // u8[1024] = 1024
#define O_FINAL  189440          // int[100] = 400
#define O_KEEPW  189840          // u64[16] = 128
#define K3C_SMEM (189840 + 128 + 32)

__global__ void k3c_final(const float* __restrict__ r0, const float* __restrict__ r1,
                          const float* __restrict__ r2, const float* __restrict__ r3,
                          const float* __restrict__ r4, const int* __restrict__ isz,
                          float* __restrict__ out) {
    extern __shared__ char sm[];
    u64* keys = (u64*)(sm + O_KEYS);
    u64* s_sel = (u64*)(sm + O_SEL);
    u32* hist = (u32*)(sm + O_HIST);
    u64* s_prefix = (u64*)(sm + O_MISC);
    int* s_krem = (int*)(sm + O_MISC + 8);
    int* s_cnt2 = (int*)(sm + O_MISC + 12);
    int* s_nkeep = (int*)(sm + O_MISC + 16);
    float* s_mc = (float*)(sm + O_MISC + 20);
    float* s_redf = (float*)(sm + O_REDF);
    float4* s_nb = (float4*)(sm + O_NB);
    float* s_area = (float*)(sm + O_AREA);
    float4* s_topb = (float4*)(sm + O_TOPB);
    float* s_tops = (float*)(sm + O_TOPS);
    int* s_lab = (int*)(sm + O_LAB);
    u8* s_valid = (u8*)(sm + O_VALID);
    int* s_final = (int*)(sm + O_FINAL);
    u64* s_keepw = (u64*)(sm + O_KEEPW);
    u64* s_mask = keys;  // reused after selection

    int img = blockIdx.x;
    int tid = threadIdx.x;
    int cnt = d_cnt[img];
    if (cnt > KCAP) cnt = KCAP;
    for (int i = tid; i < cnt; i += 1024) keys[i] = d_keys[img][i];
    __syncthreads();

    KeyArr64 kf{keys};
    u64 kth = radix_select_k(kf, cnt, KSEL, hist, s_prefix, s_krem);

    if (tid == 0) *s_cnt2 = 0;
    __syncthreads();
    for (int i = tid; i < cnt; i += 1024) {
        u64 key = keys[i];
        if (key >= kth) {
            int p = atomicAdd(s_cnt2, 1);
            if (p < 1024) s_sel[p] = key;
        }
    }
    __syncthreads();
    if (tid >= *s_cnt2) s_sel[tid] = 0;
    __syncthreads();
    bitonic_sort_1024(s_sel);

    float hF = (float)__ldg(isz + img * 2);
    float wF = (float)__ldg(isz + img * 2 + 1);

    float x1c = 0.f, y1c = 0.f, x2c = 0.f, y2c = 0.f, mylocal = 0.f;
    int lab = 0;
    bool val = false;
    if (tid < KSEL) {
        u64 key = s_sel[1023 - tid];
        u32 idx = 0xFFFFFFFFu - (u32)(key & 0xFFFFFFFFull);
        float logit = iford((u32)(key >> 32));   // exact original (or NEG if below threshold)
        val = (logit > LTHRF);
        float tops = val ? (1.f / (1.f + expf(-logit))) : NEGF;
        int row = idx / NC;
        lab = (int)(idx % NC) + 1;
        // decode box for this row
        int lvl, loc;
        row_to_lvl_loc(img, row, lvl, loc);
        const float* p;
        int hw;
        float sf;
        switch (lvl) {
            case 0: p = r0; hw = 15200; sf = 8.f; break;
            case 1: p = r1; hw = 3800; sf = 16.f; break;
            case 2: p = r2; hw = 950; sf = 32.f; break;
            case 3: p = r3; hw = 247; sf = 64.f; break;
            default: p = r4; hw = 70; sf = 128.f; break;
        }
        size_t base = (size_t)img * 4 * hw;
        float v0 = __ldg(p + base + 0 * (size_t)hw + loc);
        float v1 = __ldg(p + base + 1 * (size_t)hw + loc);
        float v2 = __ldg(p + base + 2 * (size_t)hw + loc);
        float v3 = __ldg(p + base + 3 * (size_t)hw + loc);
        float b0 = fminf(__fmul_rn(v1, sf), wF);
        float b1 = fminf(__fmul_rn(v0, sf), hF);
        float b2 = fminf(__fmul_rn(v3, sf), wF);
        float b3 = fminf(__fmul_rn(v2, sf), hF);
        b2 = fmaxf(__fadd_rn(b0, 1.f), b2);
        b3 = fmaxf(__fadd_rn(b1, 1.f), b3);
        float wm1 = __fsub_rn(wF, 1.f), hm1 = __fsub_rn(hF, 1.f);
        x1c = fminf(fmaxf(b0, 0.f), wm1);
        y1c = fminf(fmaxf(b1, 0.f), hm1);
        x2c = fminf(fmaxf(b2, 0.f), wm1);
        y2c = fminf(fmaxf(b3, 0.f), hm1);
        s_topb[tid] = make_float4(x1c, y1c, x2c, y2c);
        s_tops[tid] = tops;
        s_lab[tid] = lab;
        s_valid[tid] = val ? 1 : 0;
        if (val) mylocal = fmaxf(fmaxf(x1c, y1c), fmaxf(x2c, y2c));
    }
    s_redf[tid] = mylocal;
    __syncthreads();
    for (int s = 512; s > 0; s >>= 1) {
        if (tid < s) s_redf[tid] = fmaxf(s_redf[tid], s_redf[tid + s]);
        __syncthreads();
    }
    if (tid == 0) *s_mc = s_redf[0];
    __syncthreads();
    if (tid < KSEL) {
        float mc1 = __fadd_rn(*s_mc, 1.f);
        float o = __fmul_rn((float)lab, mc1);
        float4 nb = make_float4(__fadd_rn(x1c, o), __fadd_rn(y1c, o),
                                __fadd_rn(x2c, o), __fadd_rn(y2c, o));
        s_nb[tid] = nb;
        s_area[tid] = __fmul_rn(__fsub_rn(nb.z, nb.x), __fsub_rn(nb.w, nb.y));
    }
    __syncthreads();

    // suppression bitmask into reused keys region
    for (int t = tid; t < 16000; t += 1024) {
        int w = t / 1000;
        int i = t % 1000;
        int j0 = w * 64;
        int j1 = min(j0 + 64, i);
        u64 m = 0;
        if (j1 > j0) {
            float4 A = s_nb[i];
            float aA = s_area[i];
            for (int j = j0; j < j1; ++j) {
                float4 Bb = s_nb[j];
                float ix1 = fmaxf(A.x, Bb.x), iy1 = fmaxf(A.y, Bb.y);
                float ix2 = fminf(A.z, Bb.z), iy2 = fminf(A.w, Bb.w);
                float iw = fmaxf(__fsub_rn(ix2, ix1), 0.f);
                float ih = fmaxf(__fsub_rn(iy2, iy1), 0.f);
                float inter = __fmul_rn(iw, ih);
                float den = fmaxf(__fsub_rn(__fadd_rn(aA, s_area[j]), inter), 1e-9f);
                if (__fdiv_rn(inter, den) > 0.6f) m |= (1ull << (j - j0));
            }
        }
        s_mask[i * 16 + w] = m;
    }
    __syncthreads();

    // serial greedy scan: warp 0, lanes 0..15 own one keep word each
    if (tid < 32) {
        int lane = tid;
        u64 keepw = 0;
        int nk = 0;
        u64 next = (lane < 16) ? s_mask[lane] : 0;
        for (int i = 0; i < 1000; i++) {
            u64 rowm = next;
            next = (lane < 16 && i < 999) ? s_mask[(i + 1) * 16 + lane] : 0;
            bool sup = (rowm & keepw) != 0;
            bool any = __any_sync(0xFFFFFFFFu, sup);
            bool keep = (s_valid[i] != 0) && !any;
            if (keep) {
                if ((i >> 6) == lane) keepw |= (1ull << (i & 63));
                if (lane == 0 && nk < 100) s_final[nk] = i;
                nk++;
            }
        }
        if (lane < 16) s_keepw[lane] = keepw;
        __syncwarp();
        if (lane == 0) {
            int c = nk < 100 ? nk : 100;
            *s_nkeep = c;
            for (int i = 0; i < 1000 && c < 100; i++) {
                bool kb = (s_keepw[i >> 6] >> (i & 63)) & 1ull;
                if (!kb) s_final[c++] = i;
            }
        }
    }
    __syncthreads();

    if (tid < 100) {
        int fi = s_final[tid];
        bool v = tid < *s_nkeep;
        float4 bp = s_topb[fi];
        int base = img * 100 + tid;
        out[base * 4 + 0] = bp.x;
        out[base * 4 + 1] = bp.y;
        out[base * 4 + 2] = bp.z;
        out[base * 4 + 3] = bp.w;
        out[6400 + base] = v ? s_tops[fi] : 0.f;
        out[8000 + base] = (float)s_lab[fi];
        out[9600 + base] = v ? 1.f : 0.f;
    }
}

// ---------------- host launcher ----------------
extern "C" void kernel_launch(void* const* d_in, const int* in_sizes, int n_in,
                              void* d_out, int out_size) {
    static const int clsN[5] = {19456000, 4864000, 1216000, 316160, 89600};
    static const int regN[5] = {972800, 243200, 60800, 15808, 4480};
    const float* cls[5] = {0, 0, 0, 0, 0};
    const float* reg[5] = {0, 0, 0, 0, 0};
    const int* isz = 0;
    for (int i = 0; i < n_in; i++) {
        int s = in_sizes[i];
        if (s == 32) { isz = (const int*)d_in[i]; continue; }
        for (int l = 0; l < 5; l++) {
            if (s == clsN[l]) cls[l] = (const float*)d_in[i];
            if (s == regN[l]) reg[l] = (const float*)d_in[i];
        }
    }
    if (!isz) return;
    for (int l = 0; l < 5; l++) if (!cls[l] || !reg[l]) return;

    cudaFuncSetAttribute(k1_select, cudaFuncAttributeMaxDynamicSharedMemorySize, K1_SMEM);
    cudaFuncSetAttribute(k3c_final, cudaFuncAttributeMaxDynamicSharedMemorySize, K3C_SMEM);

    k0_maxlogit<<<(NB * 4750 + 255) / 256, 256>>>((const float4*)cls[0], (const float4*)cls[1]);
    k1_select<<<dim3(2, NB), 1024, K1_SMEM>>>();
    k2a_gather_hist<<<dim3((NFLAT + 255) / 256, NB), 256>>>(cls[0], cls[1], cls[2], cls[3], cls[4]);
    k3b_compact<<<dim3(NCHUNK, NB), 256>>>();
    k3c_final<<<NB, 1024, K3C_SMEM>>>(reg[0], reg[1], reg[2], reg[3], reg[4], isz, (float*)d_out);
}